// round 2
// baseline (speedup 1.0000x reference)
#include <cuda_runtime.h>
#include <math.h>

#define G_      128
#define NPG_    256
#define DIMM    512
#define HEADS_  8
#define DH_     64
#define NTOK    (G_*NPG_)                  // 32768
#define SBUF    ((size_t)NTOK * DIMM)      // 16,777,216 floats

// ---------------- scratch pool (device global; no runtime allocation) ----------------
// Layout (units of SBUF floats), liveness-checked:
//   [0,1) xn        [1,2) qn -> later xn2
//   [2,3) q         [3,5) kv          [5,6) o
//   [6,7) ind -> later x2
//   FF hidden h (4*SBUF) reuses [2,6) after q/kv/o are dead.
__device__ float g_pool[7 * SBUF];

// ---------------- group layernorm over one group's (NPG, DIM) ----------------
__global__ __launch_bounds__(512) void group_ln_k(
    const float* __restrict__ x, const float* __restrict__ w,
    const float* __restrict__ b, float* __restrict__ y)
{
    const int g = blockIdx.x;
    const float4* xg = (const float4*)(x + (size_t)g * NPG_ * DIMM);
    float4*       yg = (float4*)      (y + (size_t)g * NPG_ * DIMM);
    const float4* w4 = (const float4*)w;
    const float4* b4 = (const float4*)b;
    const int per = NPG_ * DIMM / 4;    // 32768 float4

    float s = 0.f, s2 = 0.f;
    for (int i = threadIdx.x; i < per; i += 512) {
        float4 v = xg[i];
        s  += (v.x + v.y) + (v.z + v.w);
        s2 += (v.x*v.x + v.y*v.y) + (v.z*v.z + v.w*v.w);
    }
    __shared__ float rs[16], rs2[16];
    unsigned lane = threadIdx.x & 31, wid = threadIdx.x >> 5;
    #pragma unroll
    for (int o = 16; o; o >>= 1) {
        s  += __shfl_down_sync(0xFFFFFFFFu, s,  o);
        s2 += __shfl_down_sync(0xFFFFFFFFu, s2, o);
    }
    if (lane == 0) { rs[wid] = s; rs2[wid] = s2; }
    __syncthreads();
    __shared__ float sm_mean, sm_inv;
    if (threadIdx.x == 0) {
        float ts = 0.f, ts2 = 0.f;
        #pragma unroll
        for (int i = 0; i < 16; i++) { ts += rs[i]; ts2 += rs2[i]; }
        const float cnt = (float)(NPG_ * DIMM);
        float mean = ts / cnt;
        float var  = ts2 / cnt - mean * mean;
        sm_mean = mean;
        sm_inv  = rsqrtf(var + 1e-5f);
    }
    __syncthreads();
    const float mean = sm_mean, inv = sm_inv;
    for (int i = threadIdx.x; i < per; i += 512) {
        float4 v = xg[i];
        float4 wv = w4[i & 127];
        float4 bv = b4[i & 127];
        float4 r;
        r.x = (v.x - mean) * inv * wv.x + bv.x;
        r.y = (v.y - mean) * inv * wv.y + bv.y;
        r.z = (v.z - mean) * inv * wv.z + bv.z;
        r.w = (v.w - mean) * inv * wv.w + bv.w;
        yg[i] = r;
    }
}

// ---------------- SGEMM: C[M,N] = A[M,K] * B[K,N] (+epilogue) ----------------
// EPI: 0 = none, 1 = +bias, 2 = gelu(+bias), 3 = +bias +residual
__device__ __forceinline__ float gelu_f(float v) {
    return 0.5f * v * (1.f + erff(v * 0.70710678118654752f));
}

template<int EPI>
__global__ __launch_bounds__(256) void sgemm_k(
    const float* __restrict__ A, const float* __restrict__ B,
    const float* __restrict__ bias, const float* __restrict__ R,
    float* __restrict__ C, int M, int N, int K)
{
    __shared__ float As[16][128];
    __shared__ float Bs[16][128];

    const int tid = threadIdx.x;
    const int bm = blockIdx.y << 7;
    const int bn = blockIdx.x << 7;
    const int tx = tid & 15, ty = tid >> 4;

    const float* Ab = A + (size_t)bm * K;
    const float* Bb = B + bn;

    float acc[8][8];
    #pragma unroll
    for (int i = 0; i < 8; i++)
        #pragma unroll
        for (int j = 0; j < 8; j++) acc[i][j] = 0.f;

    for (int k0 = 0; k0 < K; k0 += 16) {
        #pragma unroll
        for (int l = 0; l < 2; l++) {
            int idx = tid + l * 256;
            int r = idx >> 2, c4 = idx & 3;
            float4 v = *(const float4*)(Ab + (size_t)r * K + k0 + c4 * 4);
            As[c4*4+0][r] = v.x; As[c4*4+1][r] = v.y;
            As[c4*4+2][r] = v.z; As[c4*4+3][r] = v.w;
        }
        #pragma unroll
        for (int l = 0; l < 2; l++) {
            int idx = tid + l * 256;
            int r = idx >> 5, c4 = idx & 31;
            *(float4*)&Bs[r][c4*4] = *(const float4*)(Bb + (size_t)(k0 + r) * N + c4 * 4);
        }
        __syncthreads();
        #pragma unroll
        for (int kk = 0; kk < 16; kk++) {
            float a[8], b[8];
            *(float4*)(a)   = *(const float4*)&As[kk][ty*8];
            *(float4*)(a+4) = *(const float4*)&As[kk][ty*8+4];
            *(float4*)(b)   = *(const float4*)&Bs[kk][tx*8];
            *(float4*)(b+4) = *(const float4*)&Bs[kk][tx*8+4];
            #pragma unroll
            for (int i = 0; i < 8; i++)
                #pragma unroll
                for (int j = 0; j < 8; j++)
                    acc[i][j] += a[i] * b[j];
        }
        __syncthreads();
    }

    #pragma unroll
    for (int ii = 0; ii < 8; ii++) {
        const int row = bm + ty*8 + ii;
        #pragma unroll
        for (int j4 = 0; j4 < 2; j4++) {
            const int col = bn + tx*8 + j4*4;
            float vx = acc[ii][j4*4+0], vy = acc[ii][j4*4+1];
            float vz = acc[ii][j4*4+2], vw = acc[ii][j4*4+3];
            if (EPI >= 1) {
                float4 bv = *(const float4*)(bias + col);
                vx += bv.x; vy += bv.y; vz += bv.z; vw += bv.w;
            }
            if (EPI == 2) {
                vx = gelu_f(vx); vy = gelu_f(vy); vz = gelu_f(vz); vw = gelu_f(vw);
            }
            if (EPI == 3) {
                float4 rv = *(const float4*)(R + (size_t)row * N + col);
                vx += rv.x; vy += rv.y; vz += rv.z; vw += rv.w;
            }
            float4 out; out.x = vx; out.y = vy; out.z = vz; out.w = vw;
            *(float4*)(C + (size_t)row * N + col) = out;
        }
    }
}

// ---------------- per-(group,head) attention, online softmax ----------------
__global__ __launch_bounds__(256) void attn_k(
    const float* __restrict__ qbuf, const float* __restrict__ kvbuf,
    float* __restrict__ obuf)
{
    __shared__ float Ks[64 * DH_];   // 16 KB
    __shared__ float Vs[64 * DH_];   // 16 KB
    const int g = blockIdx.x, h = blockIdx.y;
    const int i = threadIdx.x;       // query row within group
    const float* kvg = kvbuf + (size_t)g * NPG_ * 2 * DIMM;

    float q[DH_];
    {
        const float* qr = qbuf + ((size_t)(g * NPG_ + i)) * DIMM + h * DH_;
        #pragma unroll
        for (int d4 = 0; d4 < 16; d4++)
            *(float4*)(q + d4*4) = *(const float4*)(qr + d4*4);
    }
    float o[DH_];
    #pragma unroll
    for (int d = 0; d < DH_; d++) o[d] = 0.f;
    float m = -1e30f, l = 0.f;

    for (int jc = 0; jc < NPG_; jc += 64) {
        __syncthreads();
        for (int t = threadIdx.x; t < 64 * 16; t += 256) {
            int j = t >> 4, d4 = t & 15;
            const float* base = kvg + (size_t)(jc + j) * (2 * DIMM) + h * DH_;
            ((float4*)Ks)[t] = *(const float4*)(base + d4 * 4);
            ((float4*)Vs)[t] = *(const float4*)(base + DIMM + d4 * 4);
        }
        __syncthreads();

        for (int jj = 0; jj < 64; jj++) {
            const float4* kr = (const float4*)(Ks + jj * DH_);
            float sa0 = 0.f, sa1 = 0.f, sa2 = 0.f, sa3 = 0.f;
            #pragma unroll
            for (int d4 = 0; d4 < 16; d4 += 4) {
                float4 k0 = kr[d4+0], k1 = kr[d4+1], k2 = kr[d4+2], k3 = kr[d4+3];
                sa0 += q[(d4+0)*4+0]*k0.x + q[(d4+0)*4+1]*k0.y + q[(d4+0)*4+2]*k0.z + q[(d4+0)*4+3]*k0.w;
                sa1 += q[(d4+1)*4+0]*k1.x + q[(d4+1)*4+1]*k1.y + q[(d4+1)*4+2]*k1.z + q[(d4+1)*4+3]*k1.w;
                sa2 += q[(d4+2)*4+0]*k2.x + q[(d4+2)*4+1]*k2.y + q[(d4+2)*4+2]*k2.z + q[(d4+2)*4+3]*k2.w;
                sa3 += q[(d4+3)*4+0]*k3.x + q[(d4+3)*4+1]*k3.y + q[(d4+3)*4+2]*k3.z + q[(d4+3)*4+3]*k3.w;
            }
            float s = ((sa0 + sa1) + (sa2 + sa3)) * 0.125f;   // * DH^-0.5

            float nm   = fmaxf(m, s);
            float corr = __expf(m - nm);
            float p    = __expf(s - nm);
            l = l * corr + p;
            const float4* vr = (const float4*)(Vs + jj * DH_);
            #pragma unroll
            for (int d4 = 0; d4 < 16; d4++) {
                float4 v4 = vr[d4];
                o[d4*4+0] = o[d4*4+0] * corr + p * v4.x;
                o[d4*4+1] = o[d4*4+1] * corr + p * v4.y;
                o[d4*4+2] = o[d4*4+2] * corr + p * v4.z;
                o[d4*4+3] = o[d4*4+3] * corr + p * v4.w;
            }
            m = nm;
        }
    }

    const float invl = 1.f / l;
    float* orow = obuf + ((size_t)(g * NPG_ + i)) * DIMM + h * DH_;
    #pragma unroll
    for (int d4 = 0; d4 < 16; d4++) {
        float4 r;
        r.x = o[d4*4+0] * invl; r.y = o[d4*4+1] * invl;
        r.z = o[d4*4+2] * invl; r.w = o[d4*4+3] * invl;
        *(float4*)(orow + d4*4) = r;
    }
}

// ---------------- elementwise add: c = a + b ----------------
__global__ void add_k(const float* __restrict__ a, const float* __restrict__ b,
                      float* __restrict__ c, int n4)
{
    int i = blockIdx.x * blockDim.x + threadIdx.x;
    if (i < n4) {
        float4 av = ((const float4*)a)[i];
        float4 bv = ((const float4*)b)[i];
        float4 r; r.x = av.x + bv.x; r.y = av.y + bv.y;
        r.z = av.z + bv.z; r.w = av.w + bv.w;
        ((float4*)c)[i] = r;
    }
}

// ---------------- launch ----------------
extern "C" void kernel_launch(void* const* d_in, const int* in_sizes, int n_in,
                              void* d_out, int out_size)
{
    (void)in_sizes; (void)n_in; (void)out_size;
    const float* x        = (const float*)d_in[0];
    const float* queries  = (const float*)d_in[1];
    /* d_in[2] = batch (int64) — unused */
    const float* ln_seq_w = (const float*)d_in[3];
    const float* ln_seq_b = (const float*)d_in[4];
    const float* ln_q_w   = (const float*)d_in[5];
    const float* ln_q_b   = (const float*)d_in[6];
    const float* a1_Wq    = (const float*)d_in[7];
    const float* a1_Wkv   = (const float*)d_in[8];
    const float* a1_Wo    = (const float*)d_in[9];
    const float* a1_bo    = (const float*)d_in[10];
    const float* a2_Wq    = (const float*)d_in[11];
    const float* a2_Wkv   = (const float*)d_in[12];
    const float* a2_Wo    = (const float*)d_in[13];
    const float* a2_bo    = (const float*)d_in[14];
    const float* ff_ln_w  = (const float*)d_in[15];
    const float* ff_ln_b  = (const float*)d_in[16];
    const float* ff_W1    = (const float*)d_in[17];
    const float* ff_b1    = (const float*)d_in[18];
    const float* ff_W2    = (const float*)d_in[19];
    const float* ff_b2    = (const float*)d_in[20];

    float* out_x = (float*)d_out;                       // x_out
    float* out_q = out_x + SBUF;                        // q2

    float* pool;
    cudaGetSymbolAddress((void**)&pool, g_pool);
    float* p_xn  = pool;               // [0,1)
    float* p_qn  = pool + 1 * SBUF;    // [1,2) -> later xn2
    float* p_q   = pool + 2 * SBUF;    // [2,3)
    float* p_kv  = pool + 3 * SBUF;    // [3,5)
    float* p_o   = pool + 5 * SBUF;    // [5,6)
    float* p_ind = pool + 6 * SBUF;    // [6,7) -> later x2
    float* p_xn2 = p_qn;               // reuse (qn dead after a1_Wq)
    float* p_x2  = p_ind;              // reuse (ind dead after a2_Wkv + add)
    float* p_h   = pool + 2 * SBUF;    // [2,6): q/kv/o dead by FF stage

    const dim3 gemm512 (DIMM/128,     NTOK/128);   // (4, 256)
    const dim3 gemm1024(2*DIMM/128,   NTOK/128);   // (8, 256)
    const dim3 gemm2048(4*DIMM/128,   NTOK/128);   // (16, 256)
    const dim3 attng(G_, HEADS_);
    const int n4 = NTOK * DIMM / 4;

    // LayerNorms
    group_ln_k<<<G_, 512>>>(x,       ln_seq_w, ln_seq_b, p_xn);
    group_ln_k<<<G_, 512>>>(queries, ln_q_w,   ln_q_b,   p_qn);

    // Attention 1: induced = attn(qn, xn)
    sgemm_k<0><<<gemm512,  256>>>(p_qn, a1_Wq,  nullptr, nullptr, p_q,  NTOK, DIMM,   DIMM);
    sgemm_k<0><<<gemm1024, 256>>>(p_xn, a1_Wkv, nullptr, nullptr, p_kv, NTOK, 2*DIMM, DIMM);
    attn_k<<<attng, 256>>>(p_q, p_kv, p_o);
    sgemm_k<1><<<gemm512,  256>>>(p_o, a1_Wo, a1_bo, nullptr, p_ind, NTOK, DIMM, DIMM);

    // q2 = induced + queries  -> second half of output
    add_k<<<(n4 + 255)/256, 256>>>(p_ind, queries, out_q, n4);

    // Attention 2: out = attn(xn, induced); x2 = out + x (fused residual)
    sgemm_k<0><<<gemm512,  256>>>(p_xn,  a2_Wq,  nullptr, nullptr, p_q,  NTOK, DIMM,   DIMM);
    sgemm_k<0><<<gemm1024, 256>>>(p_ind, a2_Wkv, nullptr, nullptr, p_kv, NTOK, 2*DIMM, DIMM);
    attn_k<<<attng, 256>>>(p_q, p_kv, p_o);
    sgemm_k<3><<<gemm512,  256>>>(p_o, a2_Wo, a2_bo, x, p_x2, NTOK, DIMM, DIMM);

    // FF block
    group_ln_k<<<G_, 512>>>(p_x2, ff_ln_w, ff_ln_b, p_xn2);
    sgemm_k<2><<<gemm2048, 256>>>(p_xn2, ff_W1, ff_b1, nullptr, p_h,   NTOK, 4*DIMM, DIMM);
    sgemm_k<3><<<gemm512,  256>>>(p_h,   ff_W2, ff_b2, p_xn2,  out_x, NTOK, DIMM,   4*DIMM);
}

// round 6
// speedup vs baseline: 1.8299x; 1.8299x over previous
#include <cuda_runtime.h>
#include <cuda_bf16.h>
#include <math.h>
#include <stdint.h>

#define G_      128
#define NPG_    256
#define DIMM    512
#define HEADS_  8
#define DH_     64
#define NTOK    (G_*NPG_)                  // 32768
#define SBUF    ((size_t)NTOK * DIMM)      // 16,777,216 elems

// ---------------- scratch (device globals; total ~400 MB) ----------------
// fp32 pool (3*SBUF = 192MB): [0] q -> later x2, [1,3) kv -> later xn2@[1]
__device__ float g_pool[3 * SBUF];
// bf16 pairs (6*SBUF = 192MB):
//  attention era: xn [0,2)  qn->o [2,4)  ind [4,6)
//  FF era:        xn2 [0,2)  h(half tokens) [2,6)
__device__ __nv_bfloat16 g_act[6 * SBUF];
// weights hi at [0, WTOT), lo at [WTOT, 2*WTOT)  (16MB)
#define WTOT 4194304
__device__ __nv_bfloat16 g_wt[2 * WTOT];

// ================= helpers =================
__device__ __forceinline__ uint32_t smem_u32(const void* p) {
    uint32_t a;
    asm("{ .reg .u64 t; cvta.to.shared.u64 t, %1; cvt.u32.u64 %0, t; }" : "=r"(a) : "l"(p));
    return a;
}
__device__ __forceinline__ void cp16(uint32_t dst, const void* src) {
    asm volatile("cp.async.cg.shared.global [%0], [%1], 16;" :: "r"(dst), "l"(src));
}
#define CP_COMMIT() asm volatile("cp.async.commit_group;")
#define CP_WAIT1()  asm volatile("cp.async.wait_group 1;")

__device__ __forceinline__ void ldsm4(uint32_t* r, uint32_t addr) {
    asm volatile("ldmatrix.sync.aligned.m8n8.x4.shared.b16 {%0,%1,%2,%3}, [%4];"
        : "=r"(r[0]), "=r"(r[1]), "=r"(r[2]), "=r"(r[3]) : "r"(addr));
}
__device__ __forceinline__ void ldsm4t(uint32_t* r, uint32_t addr) {
    asm volatile("ldmatrix.sync.aligned.m8n8.x4.trans.shared.b16 {%0,%1,%2,%3}, [%4];"
        : "=r"(r[0]), "=r"(r[1]), "=r"(r[2]), "=r"(r[3]) : "r"(addr));
}
__device__ __forceinline__ void mma16816(float* d, const uint32_t* a, const uint32_t* b) {
    asm volatile("mma.sync.aligned.m16n8k16.row.col.f32.bf16.bf16.f32 "
        "{%0,%1,%2,%3}, {%4,%5,%6,%7}, {%8,%9}, {%0,%1,%2,%3};"
        : "+f"(d[0]), "+f"(d[1]), "+f"(d[2]), "+f"(d[3])
        : "r"(a[0]), "r"(a[1]), "r"(a[2]), "r"(a[3]), "r"(b[0]), "r"(b[1]));
}
__device__ __forceinline__ void splitf(float x, __nv_bfloat16& h, __nv_bfloat16& l) {
    h = __float2bfloat16_rn(x);
    l = __float2bfloat16_rn(x - __bfloat162float(h));
}
__device__ __forceinline__ float gelu_f(float v) {
    return 0.5f * v * (1.f + erff(v * 0.70710678118654752f));
}

// ================= bf16x3 tensor-core GEMM =================
// C[M,N] = (Ahi+Alo)[M,K] @ (Bhi+Blo)[K,N] via hi*hi + hi*lo + lo*hi, fp32 acc.
// Tile 128x128, BK=32, 3-stage cp.async pipeline, 8 warps (2m x 4n), warp tile 64x32.
// EPI: 0 none, 1 +bias, 2 +bias+gelu, 3 +bias then (+residual into fp32 C only)
// OUT: 0 fp32 only, 1 fp32 + bf16 pair (pair is PRE-residual), 2 bf16 pair only
#define BM 128
#define BN 128
#define BK 32
#define A_PITCH 80
#define B_PITCH 272
#define A_BYTES (BM*A_PITCH)                 // 10240
#define B_BYTES (BK*B_PITCH)                 // 8704
#define STAGE_B (2*A_BYTES + 2*B_BYTES)      // 37888
#define NSTG 3
#define GEMM_SMEM (NSTG*STAGE_B)             // 113664

template<int EPI, int OUT>
__global__ __launch_bounds__(256, 2) void gemm_bf(
    const __nv_bfloat16* __restrict__ Ahi, const __nv_bfloat16* __restrict__ Alo,
    const __nv_bfloat16* __restrict__ Bhi, const __nv_bfloat16* __restrict__ Blo,
    const float* __restrict__ bias, const float* __restrict__ R,
    float* __restrict__ C, __nv_bfloat16* __restrict__ Chi, __nv_bfloat16* __restrict__ Clo,
    int M, int N, int K)
{
    extern __shared__ __align__(16) char sm[];
    const uint32_t sb = smem_u32(sm);
    const int tid = threadIdx.x;
    const int lane = tid & 31, warp = tid >> 5;
    const int wm = warp & 1, wn = warp >> 1;
    const int bm = blockIdx.y * BM, bn = blockIdx.x * BN;
    const int CCH = K / BK;

    float acc[4][4][4];
    #pragma unroll
    for (int a = 0; a < 4; a++)
        #pragma unroll
        for (int b = 0; b < 4; b++)
            #pragma unroll
            for (int k = 0; k < 4; k++) acc[a][b][k] = 0.f;

    #define ISSUE(cc_)  do {                                                       \
        const int c_ = (cc_);                                                      \
        if (c_ < CCH) {                                                            \
            const uint32_t st_ = sb + (c_ % NSTG) * STAGE_B;                       \
            const int k0_ = c_ * BK;                                               \
            _Pragma("unroll")                                                      \
            for (int i = 0; i < 4; i++) {                                          \
                int idx = tid + i * 256;                                           \
                int sel = idx >> 9, rem = idx & 511;                               \
                int row = rem >> 2, ch = rem & 3;                                  \
                const __nv_bfloat16* s = (sel ? Alo : Ahi)                         \
                    + (size_t)(bm + row) * K + k0_ + ch * 8;                       \
                cp16(st_ + sel * A_BYTES + row * A_PITCH + ch * 16, s);            \
            }                                                                      \
            _Pragma("unroll")                                                      \
            for (int i = 0; i < 4; i++) {                                          \
                int idx = tid + i * 256;                                           \
                int sel = idx >> 9, rem = idx & 511;                               \
                int kr = rem >> 4, ch = rem & 15;                                  \
                const __nv_bfloat16* s = (sel ? Blo : Bhi)                         \
                    + (size_t)(k0_ + kr) * N + bn + ch * 8;                        \
                cp16(st_ + 2 * A_BYTES + sel * B_BYTES + kr * B_PITCH + ch * 16, s);\
            }                                                                      \
        }                                                                          \
        CP_COMMIT();                                                               \
    } while (0)

    ISSUE(0);
    ISSUE(1);

    const int r8 = lane & 7, sub = lane >> 3;
    const int subr = (sub & 1) * 8, subc = sub >> 1;

    for (int c = 0; c < CCH; ++c) {
        CP_WAIT1();
        __syncthreads();
        ISSUE(c + 2);
        const uint32_t st = sb + (c % NSTG) * STAGE_B;
        #pragma unroll
        for (int ks = 0; ks < 2; ++ks) {
            uint32_t Af[4][4], Bh_[2][4], Bl_[2][4];
            #pragma unroll
            for (int mt = 0; mt < 4; mt++) {
                int row = wm * 64 + mt * 16 + r8 + subr;
                ldsm4(Af[mt], st + row * A_PITCH + ks * 32 + subc * 16);
            }
            #pragma unroll
            for (int p = 0; p < 2; p++) {
                int kr = ks * 16 + r8 + subr;
                int nc = wn * 32 + p * 16 + subc * 8;
                ldsm4t(Bh_[p], st + 2 * A_BYTES + kr * B_PITCH + nc * 2);
            }
            #pragma unroll
            for (int mt = 0; mt < 4; mt++)
                #pragma unroll
                for (int nt = 0; nt < 4; nt++)
                    mma16816(acc[mt][nt], Af[mt], &Bh_[nt >> 1][(nt & 1) * 2]);
            #pragma unroll
            for (int p = 0; p < 2; p++) {
                int kr = ks * 16 + r8 + subr;
                int nc = wn * 32 + p * 16 + subc * 8;
                ldsm4t(Bl_[p], st + 2 * A_BYTES + B_BYTES + kr * B_PITCH + nc * 2);
            }
            #pragma unroll
            for (int mt = 0; mt < 4; mt++)
                #pragma unroll
                for (int nt = 0; nt < 4; nt++)
                    mma16816(acc[mt][nt], Af[mt], &Bl_[nt >> 1][(nt & 1) * 2]);
            #pragma unroll
            for (int mt = 0; mt < 4; mt++) {
                int row = wm * 64 + mt * 16 + r8 + subr;
                ldsm4(Af[mt], st + A_BYTES + row * A_PITCH + ks * 32 + subc * 16);
            }
            #pragma unroll
            for (int mt = 0; mt < 4; mt++)
                #pragma unroll
                for (int nt = 0; nt < 4; nt++)
                    mma16816(acc[mt][nt], Af[mt], &Bh_[nt >> 1][(nt & 1) * 2]);
        }
    }

    // ---- epilogue ----
    const int g = lane >> 2, tq = lane & 3;
    #pragma unroll
    for (int mt = 0; mt < 4; mt++) {
        #pragma unroll
        for (int nt = 0; nt < 4; nt++) {
            const int row0 = bm + wm * 64 + mt * 16 + g;
            const int col  = bn + wn * 32 + nt * 8 + tq * 2;
            #pragma unroll
            for (int h2 = 0; h2 < 2; h2++) {
                const int r = row0 + h2 * 8;
                float v0 = acc[mt][nt][h2 * 2 + 0];
                float v1 = acc[mt][nt][h2 * 2 + 1];
                if (EPI >= 1) { v0 += bias[col]; v1 += bias[col + 1]; }
                if (EPI == 2) { v0 = gelu_f(v0); v1 = gelu_f(v1); }
                // pair captures PRE-residual value
                if (OUT >= 1) {
                    __nv_bfloat16 h0, l0, h1, l1;
                    splitf(v0, h0, l0); splitf(v1, h1, l1);
                    *(__nv_bfloat162*)(Chi + (size_t)r * N + col) = __nv_bfloat162(h0, h1);
                    *(__nv_bfloat162*)(Clo + (size_t)r * N + col) = __nv_bfloat162(l0, l1);
                }
                if (EPI == 3) {
                    const float2 rv = *(const float2*)(R + (size_t)r * N + col);
                    v0 += rv.x; v1 += rv.y;
                }
                if (OUT != 2)
                    *(float2*)(C + (size_t)r * N + col) = make_float2(v0, v1);
            }
        }
    }
    #undef ISSUE
}

// ================= weight split kernel =================
__global__ void cvt_k(const float* __restrict__ x,
                      __nv_bfloat16* __restrict__ h, __nv_bfloat16* __restrict__ l, int n4)
{
    int i = blockIdx.x * blockDim.x + threadIdx.x;
    if (i < n4) {
        float4 v = ((const float4*)x)[i];
        __nv_bfloat16 h0,l0,h1,l1,h2,l2,h3,l3;
        splitf(v.x,h0,l0); splitf(v.y,h1,l1); splitf(v.z,h2,l2); splitf(v.w,h3,l3);
        ((__nv_bfloat162*)h)[i*2]   = __nv_bfloat162(h0,h1);
        ((__nv_bfloat162*)h)[i*2+1] = __nv_bfloat162(h2,h3);
        ((__nv_bfloat162*)l)[i*2]   = __nv_bfloat162(l0,l1);
        ((__nv_bfloat162*)l)[i*2+1] = __nv_bfloat162(l2,l3);
    }
}

// ================= group layernorm =================
// MODE 0: bf16 pair only; MODE 1: fp32 + bf16 pair
template<int MODE>
__global__ __launch_bounds__(512) void group_ln_k(
    const float* __restrict__ x, const float* __restrict__ w, const float* __restrict__ b,
    float* __restrict__ y, __nv_bfloat16* __restrict__ yh, __nv_bfloat16* __restrict__ yl)
{
    const int g = blockIdx.x;
    const float4* xg = (const float4*)(x + (size_t)g * NPG_ * DIMM);
    const float4* w4 = (const float4*)w;
    const float4* b4 = (const float4*)b;
    const int per = NPG_ * DIMM / 4;

    float s = 0.f, s2 = 0.f;
    for (int i = threadIdx.x; i < per; i += 512) {
        float4 v = xg[i];
        s  += (v.x + v.y) + (v.z + v.w);
        s2 += (v.x*v.x + v.y*v.y) + (v.z*v.z + v.w*v.w);
    }
    __shared__ float rs[16], rs2[16];
    unsigned lane = threadIdx.x & 31, wid = threadIdx.x >> 5;
    #pragma unroll
    for (int o = 16; o; o >>= 1) {
        s  += __shfl_down_sync(0xFFFFFFFFu, s,  o);
        s2 += __shfl_down_sync(0xFFFFFFFFu, s2, o);
    }
    if (lane == 0) { rs[wid] = s; rs2[wid] = s2; }
    __syncthreads();
    __shared__ float sm_mean, sm_inv;
    if (threadIdx.x == 0) {
        float ts = 0.f, ts2 = 0.f;
        #pragma unroll
        for (int i = 0; i < 16; i++) { ts += rs[i]; ts2 += rs2[i]; }
        const float cnt = (float)(NPG_ * DIMM);
        float mean = ts / cnt;
        float var  = ts2 / cnt - mean * mean;
        sm_mean = mean;
        sm_inv  = rsqrtf(var + 1e-5f);
    }
    __syncthreads();
    const float mean = sm_mean, inv = sm_inv;
    float4*          yg  = MODE ? (float4*)(y + (size_t)g * NPG_ * DIMM) : nullptr;
    __nv_bfloat162*  yh2 = (__nv_bfloat162*)(yh + (size_t)g * NPG_ * DIMM);
    __nv_bfloat162*  yl2 = (__nv_bfloat162*)(yl + (size_t)g * NPG_ * DIMM);
    for (int i = threadIdx.x; i < per; i += 512) {
        float4 v = xg[i];
        float4 wv = w4[i & 127];
        float4 bv = b4[i & 127];
        float4 r;
        r.x = (v.x - mean) * inv * wv.x + bv.x;
        r.y = (v.y - mean) * inv * wv.y + bv.y;
        r.z = (v.z - mean) * inv * wv.z + bv.z;
        r.w = (v.w - mean) * inv * wv.w + bv.w;
        if (MODE) yg[i] = r;
        __nv_bfloat16 h0,l0,h1,l1,h2,l2,h3,l3;
        splitf(r.x,h0,l0); splitf(r.y,h1,l1); splitf(r.z,h2,l2); splitf(r.w,h3,l3);
        yh2[i*2]   = __nv_bfloat162(h0,h1);
        yh2[i*2+1] = __nv_bfloat162(h2,h3);
        yl2[i*2]   = __nv_bfloat162(l0,l1);
        yl2[i*2+1] = __nv_bfloat162(l2,l3);
    }
}

// ================= attention (SIMT fp32, online softmax; bf16-pair output) =================
__global__ __launch_bounds__(256) void attn_k(
    const float* __restrict__ qbuf, const float* __restrict__ kvbuf,
    __nv_bfloat16* __restrict__ oh, __nv_bfloat16* __restrict__ ol)
{
    __shared__ float Ks[64 * DH_];
    __shared__ float Vs[64 * DH_];
    const int g = blockIdx.x, h = blockIdx.y;
    const int i = threadIdx.x;
    const float* kvg = kvbuf + (size_t)g * NPG_ * 2 * DIMM;

    float q[DH_];
    {
        const float* qr = qbuf + ((size_t)(g * NPG_ + i)) * DIMM + h * DH_;
        #pragma unroll
        for (int d4 = 0; d4 < 16; d4++)
            *(float4*)(q + d4*4) = *(const float4*)(qr + d4*4);
    }
    float o[DH_];
    #pragma unroll
    for (int d = 0; d < DH_; d++) o[d] = 0.f;
    float m = -1e30f, l = 0.f;

    for (int jc = 0; jc < NPG_; jc += 64) {
        __syncthreads();
        for (int t = threadIdx.x; t < 64 * 16; t += 256) {
            int j = t >> 4, d4 = t & 15;
            const float* base = kvg + (size_t)(jc + j) * (2 * DIMM) + h * DH_;
            ((float4*)Ks)[t] = *(const float4*)(base + d4 * 4);
            ((float4*)Vs)[t] = *(const float4*)(base + DIMM + d4 * 4);
        }
        __syncthreads();

        for (int jj = 0; jj < 64; jj++) {
            const float4* kr = (const float4*)(Ks + jj * DH_);
            float sa0 = 0.f, sa1 = 0.f, sa2 = 0.f, sa3 = 0.f;
            #pragma unroll
            for (int d4 = 0; d4 < 16; d4 += 4) {
                float4 k0 = kr[d4+0], k1 = kr[d4+1], k2 = kr[d4+2], k3 = kr[d4+3];
                sa0 += q[(d4+0)*4+0]*k0.x + q[(d4+0)*4+1]*k0.y + q[(d4+0)*4+2]*k0.z + q[(d4+0)*4+3]*k0.w;
                sa1 += q[(d4+1)*4+0]*k1.x + q[(d4+1)*4+1]*k1.y + q[(d4+1)*4+2]*k1.z + q[(d4+1)*4+3]*k1.w;
                sa2 += q[(d4+2)*4+0]*k2.x + q[(d4+2)*4+1]*k2.y + q[(d4+2)*4+2]*k2.z + q[(d4+2)*4+3]*k2.w;
                sa3 += q[(d4+3)*4+0]*k3.x + q[(d4+3)*4+1]*k3.y + q[(d4+3)*4+2]*k3.z + q[(d4+3)*4+3]*k3.w;
            }
            float sc = ((sa0 + sa1) + (sa2 + sa3)) * 0.125f;

            float nm   = fmaxf(m, sc);
            float corr = __expf(m - nm);
            float p    = __expf(sc - nm);
            l = l * corr + p;
            const float4* vr = (const float4*)(Vs + jj * DH_);
            #pragma unroll
            for (int d4 = 0; d4 < 16; d4++) {
                float4 v4 = vr[d4];
                o[d4*4+0] = o[d4*4+0] * corr + p * v4.x;
                o[d4*4+1] = o[d4*4+1] * corr + p * v4.y;
                o[d4*4+2] = o[d4*4+2] * corr + p * v4.z;
                o[d4*4+3] = o[d4*4+3] * corr + p * v4.w;
            }
            m = nm;
        }
    }

    const float invl = 1.f / l;
    const size_t rb = ((size_t)(g * NPG_ + i)) * DIMM + h * DH_;
    __nv_bfloat162* oh2 = (__nv_bfloat162*)(oh + rb);
    __nv_bfloat162* ol2 = (__nv_bfloat162*)(ol + rb);
    #pragma unroll
    for (int d2 = 0; d2 < 32; d2++) {
        float v0 = o[d2*2+0] * invl, v1 = o[d2*2+1] * invl;
        __nv_bfloat16 h0,l0,h1,l1;
        splitf(v0,h0,l0); splitf(v1,h1,l1);
        oh2[d2] = __nv_bfloat162(h0,h1);
        ol2[d2] = __nv_bfloat162(l0,l1);
    }
}

// ================= launch =================
extern "C" void kernel_launch(void* const* d_in, const int* in_sizes, int n_in,
                              void* d_out, int out_size)
{
    (void)in_sizes; (void)n_in; (void)out_size;
    const float* x        = (const float*)d_in[0];
    const float* queries  = (const float*)d_in[1];
    const float* ln_seq_w = (const float*)d_in[3];
    const float* ln_seq_b = (const float*)d_in[4];
    const float* ln_q_w   = (const float*)d_in[5];
    const float* ln_q_b   = (const float*)d_in[6];
    const float* a1_Wq    = (const float*)d_in[7];
    const float* a1_Wkv   = (const float*)d_in[8];
    const float* a1_Wo    = (const float*)d_in[9];
    const float* a1_bo    = (const float*)d_in[10];
    const float* a2_Wq    = (const float*)d_in[11];
    const float* a2_Wkv   = (const float*)d_in[12];
    const float* a2_Wo    = (const float*)d_in[13];
    const float* a2_bo    = (const float*)d_in[14];
    const float* ff_ln_w  = (const float*)d_in[15];
    const float* ff_ln_b  = (const float*)d_in[16];
    const float* ff_W1    = (const float*)d_in[17];
    const float* ff_b1    = (const float*)d_in[18];
    const float* ff_W2    = (const float*)d_in[19];
    const float* ff_b2    = (const float*)d_in[20];

    float* out_x = (float*)d_out;
    float* out_q = out_x + SBUF;

    float* pool;  __nv_bfloat16* act;  __nv_bfloat16* wt;
    cudaGetSymbolAddress((void**)&pool, g_pool);
    cudaGetSymbolAddress((void**)&act,  g_act);
    cudaGetSymbolAddress((void**)&wt,   g_wt);

    float* p_q   = pool;                  // dead after attn2 -> x2
    float* p_kv  = pool + 1 * SBUF;       // dead after attn2 -> xn2
    float* p_x2  = pool;
    float* p_xn2 = pool + 1 * SBUF;

    __nv_bfloat16* xn_h = act + 0 * SBUF; __nv_bfloat16* xn_l = act + 1 * SBUF;
    __nv_bfloat16* qn_h = act + 2 * SBUF; __nv_bfloat16* qn_l = act + 3 * SBUF;
    __nv_bfloat16* o_h  = act + 2 * SBUF; __nv_bfloat16* o_l  = act + 3 * SBUF;  // overlay qn (dead)
    __nv_bfloat16* in_h = act + 4 * SBUF; __nv_bfloat16* in_l = act + 5 * SBUF;
    __nv_bfloat16* x2_h = act + 0 * SBUF; __nv_bfloat16* x2_l = act + 1 * SBUF;  // overlay xn (dead)
    __nv_bfloat16* h_h  = act + 2 * SBUF; __nv_bfloat16* h_l  = act + 4 * SBUF;  // half-token h pair

    const size_t OWQ1 = 0,        OWKV1 = 262144,  OWO1 = 786432;
    const size_t OWQ2 = 1048576,  OWKV2 = 1310720, OWO2 = 1835008;
    const size_t OW1  = 2097152,  OW2   = 3145728;
    __nv_bfloat16* wh = wt;  __nv_bfloat16* wl = wt + WTOT;

    cudaFuncSetAttribute(gemm_bf<0,0>, cudaFuncAttributeMaxDynamicSharedMemorySize, GEMM_SMEM);
    cudaFuncSetAttribute(gemm_bf<3,1>, cudaFuncAttributeMaxDynamicSharedMemorySize, GEMM_SMEM);
    cudaFuncSetAttribute(gemm_bf<2,2>, cudaFuncAttributeMaxDynamicSharedMemorySize, GEMM_SMEM);
    cudaFuncSetAttribute(gemm_bf<3,0>, cudaFuncAttributeMaxDynamicSharedMemorySize, GEMM_SMEM);

    struct { const float* s; size_t o; int n; } cv[8] = {
        {a1_Wq, OWQ1, 262144}, {a1_Wkv, OWKV1, 524288}, {a1_Wo, OWO1, 262144},
        {a2_Wq, OWQ2, 262144}, {a2_Wkv, OWKV2, 524288}, {a2_Wo, OWO2, 262144},
        {ff_W1, OW1, 1048576}, {ff_W2, OW2, 1048576} };
    for (int i = 0; i < 8; i++) {
        int n4 = cv[i].n / 4;
        cvt_k<<<(n4 + 255) / 256, 256>>>(cv[i].s, wh + cv[i].o, wl + cv[i].o, n4);
    }

    const dim3 gN512 (4,  NTOK/BM);      // (4, 256)
    const dim3 gN1024(8,  NTOK/BM);      // (8, 256)
    const dim3 attng(G_, HEADS_);

    group_ln_k<0><<<G_, 512>>>(x,       ln_seq_w, ln_seq_b, nullptr, xn_h, xn_l);
    group_ln_k<0><<<G_, 512>>>(queries, ln_q_w,   ln_q_b,   nullptr, qn_h, qn_l);

    // Attention 1: induced = attn(ln(queries), ln(x))
    gemm_bf<0,0><<<gN512,  256, GEMM_SMEM>>>(qn_h, qn_l, wh+OWQ1,  wl+OWQ1,  nullptr, nullptr,
                                             p_q,  nullptr, nullptr, NTOK, DIMM,   DIMM);
    gemm_bf<0,0><<<gN1024, 256, GEMM_SMEM>>>(xn_h, xn_l, wh+OWKV1, wl+OWKV1, nullptr, nullptr,
                                             p_kv, nullptr, nullptr, NTOK, 2*DIMM, DIMM);
    attn_k<<<attng, 256>>>(p_q, p_kv, o_h, o_l);
    // induced pair -> in_h/in_l ; q2 = induced + queries -> out_q (fused)
    gemm_bf<3,1><<<gN512,  256, GEMM_SMEM>>>(o_h, o_l, wh+OWO1, wl+OWO1, a1_bo, queries,
                                             out_q, in_h, in_l, NTOK, DIMM, DIMM);

    // Attention 2: out = attn(ln(x), induced); x2 = out + x (fused)
    gemm_bf<0,0><<<gN512,  256, GEMM_SMEM>>>(xn_h, xn_l, wh+OWQ2,  wl+OWQ2,  nullptr, nullptr,
                                             p_q,  nullptr, nullptr, NTOK, DIMM,   DIMM);
    gemm_bf<0,0><<<gN1024, 256, GEMM_SMEM>>>(in_h, in_l, wh+OWKV2, wl+OWKV2, nullptr, nullptr,
                                             p_kv, nullptr, nullptr, NTOK, 2*DIMM, DIMM);
    attn_k<<<attng, 256>>>(p_q, p_kv, o_h, o_l);
    gemm_bf<3,0><<<gN512,  256, GEMM_SMEM>>>(o_h, o_l, wh+OWO2, wl+OWO2, a2_bo, x,
                                             p_x2, nullptr, nullptr, NTOK, DIMM, DIMM);

    // FF block: LN, then two M-halves through the 4*SBUF-sized h pair buffer
    group_ln_k<1><<<G_, 512>>>(p_x2, ff_ln_w, ff_ln_b, p_xn2, x2_h, x2_l);

    const int MH = NTOK / 2;                       // 16384 rows per half
    const dim3 gFF1(4 * DIMM / BN, MH / BM);       // (16, 128)
    const dim3 gFF2(DIMM / BN,     MH / BM);       // (4, 128)
    for (int half = 0; half < 2; half++) {
        const size_t aoff = (size_t)half * MH * DIMM;
        const size_t hoff = 0;
        const size_t ooff = (size_t)half * MH * DIMM;
        gemm_bf<2,2><<<gFF1, 256, GEMM_SMEM>>>(x2_h + aoff, x2_l + aoff, wh+OW1, wl+OW1,
                                               ff_b1, nullptr,
                                               nullptr, h_h + hoff, h_l + hoff,
                                               MH, 4*DIMM, DIMM);
        gemm_bf<3,0><<<gFF2, 256, GEMM_SMEM>>>(h_h + hoff, h_l + hoff, wh+OW2, wl+OW2,
                                               ff_b2, p_xn2 + aoff,
                                               out_x + ooff, nullptr, nullptr,
                                               MH, DIMM, 4*DIMM);
    }
}